// round 10
// baseline (speedup 1.0000x reference)
#include <cuda_runtime.h>
#include <math.h>

#define T_STEPS 1000
#define BATCH   1024
#define IN_DIM  80
#define HID     128
#define OUT_DIM 10
#define TILE_R  64

typedef unsigned long long ull;

__device__ float g_xw[(size_t)T_STEPS * BATCH * HID];   // 512 MB scratch
__device__ float g_w_inT[IN_DIM * HID];                 // w_inT[k*128+h] = w_in[h*80+k]

__device__ __forceinline__ ull ffma2(ull a, ull b, ull c) {
    ull d; asm("fma.rn.f32x2 %0, %1, %2, %3;" : "=l"(d) : "l"(a), "l"(b), "l"(c)); return d;
}

// ---------------------------------------------------------------------------
// Tiny transpose of w_in (40 KB, once per launch)
// ---------------------------------------------------------------------------
__global__ void wtrans_kernel(const float* __restrict__ w_in, float* __restrict__ w_inT) {
    int idx = blockIdx.x * 256 + threadIdx.x;
    if (idx < IN_DIM * HID) {
        int k = idx >> 7, h = idx & 127;
        w_inT[idx] = w_in[h * IN_DIM + k];
    }
}

// ---------------------------------------------------------------------------
// Kernel A: xw[row][h] = ascending-k single-acc fma.rn.f32x2 chain (bitwise
// identical to R4). 256 threads, 64-row tile, 80 KB smem -> 2 CTA/SM,
// 16 warps/SM. Inner loop/k: 2x LDS.128 (w) + 4x LDS.64 (splat x) + 16 ffma2.
// Thread (hg=tid&15, rg=tid>>4, rg<16): rows rg+16i (i<4),
// h in {4hg..4hg+3} and {64+4hg..64+4hg+3}.
// ---------------------------------------------------------------------------
__global__ void __launch_bounds__(256, 2) xw_gemm_kernel(const float* __restrict__ x,
                                                         const float* __restrict__ w_inT,
                                                         float* __restrict__ xw) {
    extern __shared__ float smg[];
    float2* xs2 = (float2*)smg;                   // [64*80] splat pairs (40 KB)
    float*  ws  = smg + 2 * TILE_R * IN_DIM;      // [80][128]           (40 KB)

    long row0 = (long)blockIdx.x * TILE_R;
    int tid = threadIdx.x;

    const float* xsrc = x + row0 * IN_DIM;
    for (int idx = tid; idx < TILE_R * IN_DIM; idx += 256) {
        float v = xsrc[idx];                      // coalesced LDG
        xs2[idx] = make_float2(v, v);             // STS.64 splat
    }
    for (int idx = tid; idx < IN_DIM * HID; idx += 256)
        ws[idx] = w_inT[idx];                     // coalesced both sides
    __syncthreads();

    int hg = tid & 15;
    int rg = tid >> 4;                            // 0..15

    ull acc[4][4];
#pragma unroll
    for (int i = 0; i < 4; ++i)
#pragma unroll
        for (int j = 0; j < 4; ++j) acc[i][j] = 0ull;

#pragma unroll 10
    for (int k = 0; k < IN_DIM; ++k) {
        ulonglong2 wA = *(const ulonglong2*)&ws[k * HID + 4 * hg];        // LDS.128
        ulonglong2 wB = *(const ulonglong2*)&ws[k * HID + 64 + 4 * hg];   // LDS.128
#pragma unroll
        for (int i = 0; i < 4; ++i) {
            ull xd = *(const ull*)&xs2[(rg + 16 * i) * IN_DIM + k];       // LDS.64
            acc[i][0] = ffma2(xd, wA.x, acc[i][0]);
            acc[i][1] = ffma2(xd, wA.y, acc[i][1]);
            acc[i][2] = ffma2(xd, wB.x, acc[i][2]);
            acc[i][3] = ffma2(xd, wB.y, acc[i][3]);
        }
    }

#pragma unroll
    for (int i = 0; i < 4; ++i) {
        float* dst = &xw[(row0 + rg + 16 * i) * HID];
        ulonglong2 oA; oA.x = acc[i][0]; oA.y = acc[i][1];
        ulonglong2 oB; oB.x = acc[i][2]; oB.y = acc[i][3];
        *(ulonglong2*)&dst[4 * hg]      = oA;     // STG.128 coalesced
        *(ulonglong2*)&dst[64 + 4 * hg] = oB;
    }
}

// ---------------------------------------------------------------------------
// Kernel B: recurrence — R4 arithmetic verbatim, with a DEPTH-4 register
// prefetch ring (time loop unrolled x4) to hide the ~577-cyc DRAM latency
// of the xw stream. Warp-per-batch; lane l owns h = l,l+32,l+64,l+96.
// ---------------------------------------------------------------------------
__global__ void __launch_bounds__(256) snn_rec_kernel(const float* __restrict__ xw,
                                                      const float* __restrict__ w_rec,
                                                      const float* __restrict__ w_out,
                                                      float* __restrict__ out) {
    extern __shared__ float smem[];
    float* wr_p = smem;              // [128][128] permuted: wr_p[j*128+4*(h&31)+(h>>5)]
    float* wo_s = smem + HID * HID;  // [128][16]: wo_s[j*16+o] = w_out[o][j]

    int tid = threadIdx.x;
    for (int idx = tid; idx < HID * HID; idx += 256) {
        int h = idx >> 7, j = idx & 127;
        wr_p[(j << 7) + ((h & 31) << 2) + (h >> 5)] = w_rec[idx];
    }
    for (int idx = tid; idx < HID * 16; idx += 256) {
        int j = idx >> 4, o = idx & 15;
        wo_s[idx] = (o < OUT_DIM) ? w_out[o * HID + j] : 0.0f;
    }
    __syncthreads();

    int warp = tid >> 5, lane = tid & 31;
    int batch = blockIdx.x * 8 + warp;

    float v0 = 0.f, v1 = 0.f, v2 = 0.f, v3 = 0.f;
    float c0 = 0.f, c1 = 0.f, c2 = 0.f, c3 = 0.f;
    float vo = 0.f, io = 0.f;

    const float* xwp = xw + (size_t)batch * HID + lane;

    // depth-4 prefetch ring: slot u holds xw[t] with t === u (mod 4)
    float rx[4][4];
#pragma unroll
    for (int u = 0; u < 4; ++u) {
        const float* p = xwp + (size_t)u * (BATCH * HID);
        rx[u][0] = p[0]; rx[u][1] = p[32]; rx[u][2] = p[64]; rx[u][3] = p[96];
    }

    for (int tb = 0; tb < T_STEPS; tb += 4) {
#pragma unroll
        for (int u = 0; u < 4; ++u) {
            int t = tb + u;
            // --- LIF (exact reference expression order, separate rounding) ---
            float vd0 = __fadd_rn(v0, __fmul_rn(0.1f, __fadd_rn(__fsub_rn(0.f, v0), c0)));
            float vd1 = __fadd_rn(v1, __fmul_rn(0.1f, __fadd_rn(__fsub_rn(0.f, v1), c1)));
            float vd2 = __fadd_rn(v2, __fmul_rn(0.1f, __fadd_rn(__fsub_rn(0.f, v2), c2)));
            float vd3 = __fadd_rn(v3, __fmul_rn(0.1f, __fadd_rn(__fsub_rn(0.f, v3), c3)));
            float id0 = __fsub_rn(c0, __fmul_rn(0.2f, c0));
            float id1 = __fsub_rn(c1, __fmul_rn(0.2f, c1));
            float id2 = __fsub_rn(c2, __fmul_rn(0.2f, c2));
            float id3 = __fsub_rn(c3, __fmul_rn(0.2f, c3));
            bool z0 = __fsub_rn(vd0, 1.0f) > 0.0f;
            bool z1 = __fsub_rn(vd1, 1.0f) > 0.0f;
            bool z2 = __fsub_rn(vd2, 1.0f) > 0.0f;
            bool z3 = __fsub_rn(vd3, 1.0f) > 0.0f;
            v0 = z0 ? 0.f : vd0;
            v1 = z1 ? 0.f : vd1;
            v2 = z2 ? 0.f : vd2;
            v3 = z3 ? 0.f : vd3;

            unsigned m0 = __ballot_sync(0xffffffffu, z0);
            unsigned m1 = __ballot_sync(0xffffffffu, z1);
            unsigned m2 = __ballot_sync(0xffffffffu, z2);
            unsigned m3 = __ballot_sync(0xffffffffu, z3);

            // consume ring slot u, then refill it with xw[t+4] (clamped)
            float x0 = rx[u][0], x1 = rx[u][1], x2 = rx[u][2], x3 = rx[u][3];
            {
                int tn = (t + 4 < T_STEPS) ? t + 4 : T_STEPS - 1;
                const float* np = xwp + (size_t)tn * (BATCH * HID);
                rx[u][0] = np[0]; rx[u][1] = np[32];
                rx[u][2] = np[64]; rx[u][3] = np[96];
            }

            // --- sparse z @ w_rec.T, ascending j (bitwise == dense chain) ---
            float r0 = 0.f, r1 = 0.f, r2 = 0.f, r3 = 0.f, os = 0.f;
#define SPIKES(MM, BASE)                                                        \
            while (MM) {                                                        \
                int b = __ffs(MM) - 1; MM &= MM - 1;                            \
                int j = (BASE) + b;                                             \
                float4 w = *(const float4*)&wr_p[(j << 7) + (lane << 2)];       \
                r0 = __fadd_rn(r0, w.x); r1 = __fadd_rn(r1, w.y);               \
                r2 = __fadd_rn(r2, w.z); r3 = __fadd_rn(r3, w.w);               \
                if (lane < OUT_DIM) os = __fadd_rn(os, wo_s[(j << 4) + lane]);  \
            }
            SPIKES(m0, 0)
            SPIKES(m1, 32)
            SPIKES(m2, 64)
            SPIKES(m3, 96)
#undef SPIKES

            c0 = __fadd_rn(__fadd_rn(id0, x0), r0);
            c1 = __fadd_rn(__fadd_rn(id1, x1), r1);
            c2 = __fadd_rn(__fadd_rn(id2, x2), r2);
            c3 = __fadd_rn(__fadd_rn(id3, x3), r3);

            // --- LI readout (lanes 0..9, o = lane) ---
            if (lane < OUT_DIM) {
                float ij = __fadd_rn(io, os);
                vo = __fadd_rn(vo, __fmul_rn(0.1f, __fadd_rn(__fsub_rn(0.f, vo), ij)));
                io = __fsub_rn(ij, __fmul_rn(0.2f, ij));
            }
        }
    }

    // --- log_softmax over 10 outputs (ascending-o chains) ---
    float mx = -INFINITY;
#pragma unroll
    for (int o = 0; o < OUT_DIM; ++o)
        mx = fmaxf(mx, __shfl_sync(0xffffffffu, vo, o));
    float s = 0.f;
#pragma unroll
    for (int o = 0; o < OUT_DIM; ++o)
        s = __fadd_rn(s, expf(__fsub_rn(__shfl_sync(0xffffffffu, vo, o), mx)));
    if (lane < OUT_DIM)
        out[batch * OUT_DIM + lane] = __fsub_rn(__fsub_rn(vo, mx), logf(s));
}

// ---------------------------------------------------------------------------
extern "C" void kernel_launch(void* const* d_in, const int* in_sizes, int n_in,
                              void* d_out, int out_size) {
    const float* x     = (const float*)d_in[0];
    const float* w_in  = (const float*)d_in[1];
    const float* w_rec = (const float*)d_in[2];
    const float* w_out = (const float*)d_in[3];
    float* out = (float*)d_out;

    float* xw = nullptr;
    float* w_inT = nullptr;
    cudaGetSymbolAddress((void**)&xw, g_xw);
    cudaGetSymbolAddress((void**)&w_inT, g_w_inT);

    wtrans_kernel<<<(IN_DIM * HID + 255) / 256, 256>>>(w_in, w_inT);

    // GEMM smem: 40KB x-splat + 40KB w = 80KB -> 2 CTA/SM, 16 warps/SM
    size_t gemm_smem = (size_t)(2 * TILE_R * IN_DIM + IN_DIM * HID) * sizeof(float);
    cudaFuncSetAttribute(xw_gemm_kernel, cudaFuncAttributeMaxDynamicSharedMemorySize,
                         (int)gemm_smem);
    xw_gemm_kernel<<<(T_STEPS * BATCH) / TILE_R, 256, gemm_smem>>>(x, w_inT, xw);

    size_t rec_smem = (size_t)(HID * HID + HID * 16) * sizeof(float);
    cudaFuncSetAttribute(snn_rec_kernel, cudaFuncAttributeMaxDynamicSharedMemorySize,
                         (int)rec_smem);
    snn_rec_kernel<<<128, 256, rec_smem>>>(xw, w_rec, w_out, out);
}

// round 11
// speedup vs baseline: 1.0136x; 1.0136x over previous
#include <cuda_runtime.h>
#include <math.h>

#define T_STEPS 1000
#define BATCH   1024
#define IN_DIM  80
#define HID     128
#define OUT_DIM 10
#define TILE_R  64

typedef unsigned long long ull;

__device__ float g_xw[(size_t)T_STEPS * BATCH * HID];   // 512 MB scratch
__device__ float g_w_inT[IN_DIM * HID];                 // w_inT[k*128+h] = w_in[h*80+k]

__device__ __forceinline__ ull ffma2(ull a, ull b, ull c) {
    ull d; asm("fma.rn.f32x2 %0, %1, %2, %3;" : "=l"(d) : "l"(a), "l"(b), "l"(c)); return d;
}

// ---------------------------------------------------------------------------
// Tiny transpose of w_in (40 KB, once per launch)
// ---------------------------------------------------------------------------
__global__ void wtrans_kernel(const float* __restrict__ w_in, float* __restrict__ w_inT) {
    int idx = blockIdx.x * 256 + threadIdx.x;
    if (idx < IN_DIM * HID) {
        int k = idx >> 7, h = idx & 127;
        w_inT[idx] = w_in[h * IN_DIM + k];
    }
}

// ---------------------------------------------------------------------------
// Kernel A: xw[row][h] = ascending-k single-acc fma.rn.f32x2 chain (bitwise
// identical to R4). 256 threads, 64-row tile, 80 KB smem -> 2 CTA/SM,
// 16 warps/SM. Inner loop/k: 2x LDS.128 (w) + 4x LDS.64 (splat x) + 16 ffma2.
// Thread (hg=tid&15, rg=tid>>4, rg<16): rows rg+16i (i<4),
// h in {4hg..4hg+3} and {64+4hg..64+4hg+3}.
// ---------------------------------------------------------------------------
__global__ void __launch_bounds__(256, 2) xw_gemm_kernel(const float* __restrict__ x,
                                                         const float* __restrict__ w_inT,
                                                         float* __restrict__ xw) {
    extern __shared__ float smg[];
    float2* xs2 = (float2*)smg;                   // [64*80] splat pairs (40 KB)
    float*  ws  = smg + 2 * TILE_R * IN_DIM;      // [80][128]           (40 KB)

    long row0 = (long)blockIdx.x * TILE_R;
    int tid = threadIdx.x;

    const float* xsrc = x + row0 * IN_DIM;
    for (int idx = tid; idx < TILE_R * IN_DIM; idx += 256) {
        float v = xsrc[idx];                      // coalesced LDG
        xs2[idx] = make_float2(v, v);             // STS.64 splat
    }
    for (int idx = tid; idx < IN_DIM * HID; idx += 256)
        ws[idx] = w_inT[idx];                     // coalesced both sides
    __syncthreads();

    int hg = tid & 15;
    int rg = tid >> 4;                            // 0..15

    ull acc[4][4];
#pragma unroll
    for (int i = 0; i < 4; ++i)
#pragma unroll
        for (int j = 0; j < 4; ++j) acc[i][j] = 0ull;

#pragma unroll 10
    for (int k = 0; k < IN_DIM; ++k) {
        ulonglong2 wA = *(const ulonglong2*)&ws[k * HID + 4 * hg];        // LDS.128
        ulonglong2 wB = *(const ulonglong2*)&ws[k * HID + 64 + 4 * hg];   // LDS.128
#pragma unroll
        for (int i = 0; i < 4; ++i) {
            ull xd = *(const ull*)&xs2[(rg + 16 * i) * IN_DIM + k];       // LDS.64
            acc[i][0] = ffma2(xd, wA.x, acc[i][0]);
            acc[i][1] = ffma2(xd, wA.y, acc[i][1]);
            acc[i][2] = ffma2(xd, wB.x, acc[i][2]);
            acc[i][3] = ffma2(xd, wB.y, acc[i][3]);
        }
    }

#pragma unroll
    for (int i = 0; i < 4; ++i) {
        float* dst = &xw[(row0 + rg + 16 * i) * HID];
        ulonglong2 oA; oA.x = acc[i][0]; oA.y = acc[i][1];
        ulonglong2 oB; oB.x = acc[i][2]; oB.y = acc[i][3];
        *(ulonglong2*)&dst[4 * hg]      = oA;     // STG.128 coalesced
        *(ulonglong2*)&dst[64 + 4 * hg] = oB;
    }
}

// ---------------------------------------------------------------------------
// Kernel B: recurrence — R4 arithmetic verbatim, with a DEPTH-4 register
// prefetch ring (time loop unrolled x4) to hide the ~577-cyc DRAM latency
// of the xw stream. Warp-per-batch; lane l owns h = l,l+32,l+64,l+96.
// ---------------------------------------------------------------------------
__global__ void __launch_bounds__(256) snn_rec_kernel(const float* __restrict__ xw,
                                                      const float* __restrict__ w_rec,
                                                      const float* __restrict__ w_out,
                                                      float* __restrict__ out) {
    extern __shared__ float smem[];
    float* wr_p = smem;              // [128][128] permuted: wr_p[j*128+4*(h&31)+(h>>5)]
    float* wo_s = smem + HID * HID;  // [128][16]: wo_s[j*16+o] = w_out[o][j]

    int tid = threadIdx.x;
    for (int idx = tid; idx < HID * HID; idx += 256) {
        int h = idx >> 7, j = idx & 127;
        wr_p[(j << 7) + ((h & 31) << 2) + (h >> 5)] = w_rec[idx];
    }
    for (int idx = tid; idx < HID * 16; idx += 256) {
        int j = idx >> 4, o = idx & 15;
        wo_s[idx] = (o < OUT_DIM) ? w_out[o * HID + j] : 0.0f;
    }
    __syncthreads();

    int warp = tid >> 5, lane = tid & 31;
    int batch = blockIdx.x * 8 + warp;

    float v0 = 0.f, v1 = 0.f, v2 = 0.f, v3 = 0.f;
    float c0 = 0.f, c1 = 0.f, c2 = 0.f, c3 = 0.f;
    float vo = 0.f, io = 0.f;

    const float* xwp = xw + (size_t)batch * HID + lane;

    // depth-4 prefetch ring: slot u holds xw[t] with t === u (mod 4)
    float rx[4][4];
#pragma unroll
    for (int u = 0; u < 4; ++u) {
        const float* p = xwp + (size_t)u * (BATCH * HID);
        rx[u][0] = p[0]; rx[u][1] = p[32]; rx[u][2] = p[64]; rx[u][3] = p[96];
    }

    for (int tb = 0; tb < T_STEPS; tb += 4) {
#pragma unroll
        for (int u = 0; u < 4; ++u) {
            int t = tb + u;
            // --- LIF (exact reference expression order, separate rounding) ---
            float vd0 = __fadd_rn(v0, __fmul_rn(0.1f, __fadd_rn(__fsub_rn(0.f, v0), c0)));
            float vd1 = __fadd_rn(v1, __fmul_rn(0.1f, __fadd_rn(__fsub_rn(0.f, v1), c1)));
            float vd2 = __fadd_rn(v2, __fmul_rn(0.1f, __fadd_rn(__fsub_rn(0.f, v2), c2)));
            float vd3 = __fadd_rn(v3, __fmul_rn(0.1f, __fadd_rn(__fsub_rn(0.f, v3), c3)));
            float id0 = __fsub_rn(c0, __fmul_rn(0.2f, c0));
            float id1 = __fsub_rn(c1, __fmul_rn(0.2f, c1));
            float id2 = __fsub_rn(c2, __fmul_rn(0.2f, c2));
            float id3 = __fsub_rn(c3, __fmul_rn(0.2f, c3));
            bool z0 = __fsub_rn(vd0, 1.0f) > 0.0f;
            bool z1 = __fsub_rn(vd1, 1.0f) > 0.0f;
            bool z2 = __fsub_rn(vd2, 1.0f) > 0.0f;
            bool z3 = __fsub_rn(vd3, 1.0f) > 0.0f;
            v0 = z0 ? 0.f : vd0;
            v1 = z1 ? 0.f : vd1;
            v2 = z2 ? 0.f : vd2;
            v3 = z3 ? 0.f : vd3;

            unsigned m0 = __ballot_sync(0xffffffffu, z0);
            unsigned m1 = __ballot_sync(0xffffffffu, z1);
            unsigned m2 = __ballot_sync(0xffffffffu, z2);
            unsigned m3 = __ballot_sync(0xffffffffu, z3);

            // consume ring slot u, then refill it with xw[t+4] (clamped)
            float x0 = rx[u][0], x1 = rx[u][1], x2 = rx[u][2], x3 = rx[u][3];
            {
                int tn = (t + 4 < T_STEPS) ? t + 4 : T_STEPS - 1;
                const float* np = xwp + (size_t)tn * (BATCH * HID);
                rx[u][0] = np[0]; rx[u][1] = np[32];
                rx[u][2] = np[64]; rx[u][3] = np[96];
            }

            // --- sparse z @ w_rec.T, ascending j (bitwise == dense chain) ---
            float r0 = 0.f, r1 = 0.f, r2 = 0.f, r3 = 0.f, os = 0.f;
#define SPIKES(MM, BASE)                                                        \
            while (MM) {                                                        \
                int b = __ffs(MM) - 1; MM &= MM - 1;                            \
                int j = (BASE) + b;                                             \
                float4 w = *(const float4*)&wr_p[(j << 7) + (lane << 2)];       \
                r0 = __fadd_rn(r0, w.x); r1 = __fadd_rn(r1, w.y);               \
                r2 = __fadd_rn(r2, w.z); r3 = __fadd_rn(r3, w.w);               \
                if (lane < OUT_DIM) os = __fadd_rn(os, wo_s[(j << 4) + lane]);  \
            }
            SPIKES(m0, 0)
            SPIKES(m1, 32)
            SPIKES(m2, 64)
            SPIKES(m3, 96)
#undef SPIKES

            c0 = __fadd_rn(__fadd_rn(id0, x0), r0);
            c1 = __fadd_rn(__fadd_rn(id1, x1), r1);
            c2 = __fadd_rn(__fadd_rn(id2, x2), r2);
            c3 = __fadd_rn(__fadd_rn(id3, x3), r3);

            // --- LI readout (lanes 0..9, o = lane) ---
            if (lane < OUT_DIM) {
                float ij = __fadd_rn(io, os);
                vo = __fadd_rn(vo, __fmul_rn(0.1f, __fadd_rn(__fsub_rn(0.f, vo), ij)));
                io = __fsub_rn(ij, __fmul_rn(0.2f, ij));
            }
        }
    }

    // --- log_softmax over 10 outputs (ascending-o chains) ---
    float mx = -INFINITY;
#pragma unroll
    for (int o = 0; o < OUT_DIM; ++o)
        mx = fmaxf(mx, __shfl_sync(0xffffffffu, vo, o));
    float s = 0.f;
#pragma unroll
    for (int o = 0; o < OUT_DIM; ++o)
        s = __fadd_rn(s, expf(__fsub_rn(__shfl_sync(0xffffffffu, vo, o), mx)));
    if (lane < OUT_DIM)
        out[batch * OUT_DIM + lane] = __fsub_rn(__fsub_rn(vo, mx), logf(s));
}

// ---------------------------------------------------------------------------
extern "C" void kernel_launch(void* const* d_in, const int* in_sizes, int n_in,
                              void* d_out, int out_size) {
    const float* x     = (const float*)d_in[0];
    const float* w_in  = (const float*)d_in[1];
    const float* w_rec = (const float*)d_in[2];
    const float* w_out = (const float*)d_in[3];
    float* out = (float*)d_out;

    float* xw = nullptr;
    float* w_inT = nullptr;
    cudaGetSymbolAddress((void**)&xw, g_xw);
    cudaGetSymbolAddress((void**)&w_inT, g_w_inT);

    wtrans_kernel<<<(IN_DIM * HID + 255) / 256, 256>>>(w_in, w_inT);

    // GEMM smem: 40KB x-splat + 40KB w = 80KB -> 2 CTA/SM, 16 warps/SM
    size_t gemm_smem = (size_t)(2 * TILE_R * IN_DIM + IN_DIM * HID) * sizeof(float);
    cudaFuncSetAttribute(xw_gemm_kernel, cudaFuncAttributeMaxDynamicSharedMemorySize,
                         (int)gemm_smem);
    xw_gemm_kernel<<<(T_STEPS * BATCH) / TILE_R, 256, gemm_smem>>>(x, w_inT, xw);

    size_t rec_smem = (size_t)(HID * HID + HID * 16) * sizeof(float);
    cudaFuncSetAttribute(snn_rec_kernel, cudaFuncAttributeMaxDynamicSharedMemorySize,
                         (int)rec_smem);
    snn_rec_kernel<<<128, 256, rec_smem>>>(xw, w_rec, w_out, out);
}

// round 12
// speedup vs baseline: 1.3930x; 1.3743x over previous
#include <cuda_runtime.h>
#include <math.h>

#define T_STEPS 1000
#define BATCH   1024
#define IN_DIM  80
#define HID     128
#define OUT_DIM 10
#define WPAD    130            // padded w row stride (even -> LDS.64 aligned)

typedef unsigned long long ull;

__device__ float g_xw[(size_t)T_STEPS * BATCH * HID];   // 512 MB scratch

__device__ __forceinline__ ull pk2(float lo, float hi) {
    ull r; asm("mov.b64 %0, {%1, %2};" : "=l"(r) : "f"(lo), "f"(hi)); return r;
}
__device__ __forceinline__ ull ffma2(ull a, ull b, ull c) {
    ull d; asm("fma.rn.f32x2 %0, %1, %2, %3;" : "=l"(d) : "l"(a), "l"(b), "l"(c)); return d;
}

// ---------------------------------------------------------------------------
// Kernel A (R4 GEMM + in-kernel w transpose): xw[row][h] = ascending-k
// single-acc fma.rn.f32x2 chain — bitwise identical to R4.
// CTA: 128 threads, 64 rows x 128 h; thread tile 8 rows (rg+8i) x 8 h
// (pairs 2hg+32j). smem 62.3 KB -> 3 CTA/SM (12 warps/SM).
// ---------------------------------------------------------------------------
__global__ void __launch_bounds__(128) xw_gemm_kernel(const float* __restrict__ x,
                                                      const float* __restrict__ w_in,
                                                      float* __restrict__ xw) {
    extern __shared__ float sm[];
    float* xs = sm;                   // [64][81] padded rows
    float* ws = sm + 64 * 81;         // [80][WPAD] transposed: ws[k*WPAD+h]

    long row0 = (long)blockIdx.x * 64;
    int tid = threadIdx.x;

    const float* xsrc = x + row0 * IN_DIM;
    for (int idx = tid; idx < 64 * IN_DIM; idx += 128) {
        int r = idx / IN_DIM, k = idx - r * IN_DIM;
        xs[r * 81 + k] = xsrc[idx];                 // coalesced LDG
    }
    for (int idx = tid; idx < HID * IN_DIM; idx += 128) {
        int h = idx / IN_DIM, k = idx - h * IN_DIM;
        ws[k * WPAD + h] = w_in[idx];               // coalesced LDG, ~2-way STS
    }
    __syncthreads();

    int hg = tid & 15;        // h-pairs 2hg + 32j (j<4)
    int rg = tid >> 4;        // rows rg + 8i (i<8)

    ull acc[8][4];
#pragma unroll
    for (int i = 0; i < 8; ++i)
#pragma unroll
        for (int j = 0; j < 4; ++j) acc[i][j] = 0ull;

#pragma unroll 10
    for (int k = 0; k < IN_DIM; ++k) {
        ull wp[4];
#pragma unroll
        for (int j = 0; j < 4; ++j)
            wp[j] = *(const ull*)&ws[k * WPAD + 2 * hg + 32 * j];  // LDS.64, conflict-free
        float xv[8];
#pragma unroll
        for (int i = 0; i < 8; ++i)
            xv[i] = xs[(rg + 8 * i) * 81 + k];      // broadcast/conflict-free scalar LDS
#pragma unroll
        for (int i = 0; i < 8; ++i) {
            ull xd = pk2(xv[i], xv[i]);
#pragma unroll
            for (int j = 0; j < 4; ++j)
                acc[i][j] = ffma2(xd, wp[j], acc[i][j]);
        }
    }

#pragma unroll
    for (int i = 0; i < 8; ++i) {
        float* dst = &xw[(row0 + rg + 8 * i) * HID];
#pragma unroll
        for (int j = 0; j < 4; ++j)
            *(ull*)&dst[2 * hg + 32 * j] = acc[i][j];   // STG.64, coalesced
    }
}

// ---------------------------------------------------------------------------
// Kernel B: recurrence — R4 arithmetic verbatim, prefetch distance 2.
// Warp-per-batch, no barriers; lane l owns h = l, l+32, l+64, l+96.
// Ballot masks give ascending-j spike walk (bitwise == dense fma chain).
// wr_p permuted for conflict-free LDS.128 per spike.
// ---------------------------------------------------------------------------
__global__ void __launch_bounds__(256) snn_rec_kernel(const float* __restrict__ xw,
                                                      const float* __restrict__ w_rec,
                                                      const float* __restrict__ w_out,
                                                      float* __restrict__ out) {
    extern __shared__ float smem[];
    float* wr_p = smem;              // [128][128] permuted: wr_p[j*128+4*(h&31)+(h>>5)]
    float* wo_s = smem + HID * HID;  // [128][16]: wo_s[j*16+o] = w_out[o][j]

    int tid = threadIdx.x;
    for (int idx = tid; idx < HID * HID; idx += 256) {
        int h = idx >> 7, j = idx & 127;
        wr_p[(j << 7) + ((h & 31) << 2) + (h >> 5)] = w_rec[idx];
    }
    for (int idx = tid; idx < HID * 16; idx += 256) {
        int j = idx >> 4, o = idx & 15;
        wo_s[idx] = (o < OUT_DIM) ? w_out[o * HID + j] : 0.0f;
    }
    __syncthreads();

    int warp = tid >> 5, lane = tid & 31;
    int batch = blockIdx.x * 8 + warp;

    float v0 = 0.f, v1 = 0.f, v2 = 0.f, v3 = 0.f;
    float c0 = 0.f, c1 = 0.f, c2 = 0.f, c3 = 0.f;
    float vo = 0.f, io = 0.f;

    const float* xwp = xw + (size_t)batch * HID + lane;

    // prefetch pipeline, distance 2
    float x0 = xwp[0], x1 = xwp[32], x2 = xwp[64], x3 = xwp[96];
    const float* p1 = xwp + (size_t)(BATCH * HID);
    float a0 = p1[0], a1 = p1[32], a2 = p1[64], a3 = p1[96];

    for (int t = 0; t < T_STEPS; ++t) {
        // --- LIF (exact reference expression order, separate rounding) ---
        float vd0 = __fadd_rn(v0, __fmul_rn(0.1f, __fadd_rn(__fsub_rn(0.f, v0), c0)));
        float vd1 = __fadd_rn(v1, __fmul_rn(0.1f, __fadd_rn(__fsub_rn(0.f, v1), c1)));
        float vd2 = __fadd_rn(v2, __fmul_rn(0.1f, __fadd_rn(__fsub_rn(0.f, v2), c2)));
        float vd3 = __fadd_rn(v3, __fmul_rn(0.1f, __fadd_rn(__fsub_rn(0.f, v3), c3)));
        float id0 = __fsub_rn(c0, __fmul_rn(0.2f, c0));
        float id1 = __fsub_rn(c1, __fmul_rn(0.2f, c1));
        float id2 = __fsub_rn(c2, __fmul_rn(0.2f, c2));
        float id3 = __fsub_rn(c3, __fmul_rn(0.2f, c3));
        bool z0 = __fsub_rn(vd0, 1.0f) > 0.0f;
        bool z1 = __fsub_rn(vd1, 1.0f) > 0.0f;
        bool z2 = __fsub_rn(vd2, 1.0f) > 0.0f;
        bool z3 = __fsub_rn(vd3, 1.0f) > 0.0f;
        v0 = z0 ? 0.f : vd0;
        v1 = z1 ? 0.f : vd1;
        v2 = z2 ? 0.f : vd2;
        v3 = z3 ? 0.f : vd3;

        unsigned m0 = __ballot_sync(0xffffffffu, z0);
        unsigned m1 = __ballot_sync(0xffffffffu, z1);
        unsigned m2 = __ballot_sync(0xffffffffu, z2);
        unsigned m3 = __ballot_sync(0xffffffffu, z3);

        // prefetch xw[t+2] (clamped; duplicate tail loads are harmless)
        int t2 = (t + 2 < T_STEPS) ? t + 2 : T_STEPS - 1;
        const float* p2 = xwp + (size_t)t2 * (BATCH * HID);
        float b0 = p2[0], b1 = p2[32], b2 = p2[64], b3 = p2[96];

        // --- sparse z @ w_rec.T, ascending j (bitwise == dense chain) ---
        float r0 = 0.f, r1 = 0.f, r2 = 0.f, r3 = 0.f, os = 0.f;
#define SPIKES(MM, BASE)                                                        \
        while (MM) {                                                            \
            int b = __ffs(MM) - 1; MM &= MM - 1;                                \
            int j = (BASE) + b;                                                 \
            float4 w = *(const float4*)&wr_p[(j << 7) + (lane << 2)];           \
            r0 = __fadd_rn(r0, w.x); r1 = __fadd_rn(r1, w.y);                   \
            r2 = __fadd_rn(r2, w.z); r3 = __fadd_rn(r3, w.w);                   \
            if (lane < OUT_DIM) os = __fadd_rn(os, wo_s[(j << 4) + lane]);      \
        }
        SPIKES(m0, 0)
        SPIKES(m1, 32)
        SPIKES(m2, 64)
        SPIKES(m3, 96)
#undef SPIKES

        c0 = __fadd_rn(__fadd_rn(id0, x0), r0);
        c1 = __fadd_rn(__fadd_rn(id1, x1), r1);
        c2 = __fadd_rn(__fadd_rn(id2, x2), r2);
        c3 = __fadd_rn(__fadd_rn(id3, x3), r3);

        // --- LI readout (lanes 0..9, o = lane) ---
        if (lane < OUT_DIM) {
            float ij = __fadd_rn(io, os);
            vo = __fadd_rn(vo, __fmul_rn(0.1f, __fadd_rn(__fsub_rn(0.f, vo), ij)));
            io = __fsub_rn(ij, __fmul_rn(0.2f, ij));
        }

        x0 = a0; x1 = a1; x2 = a2; x3 = a3;
        a0 = b0; a1 = b1; a2 = b2; a3 = b3;
    }

    // --- log_softmax over 10 outputs (ascending-o chains) ---
    float mx = -INFINITY;
#pragma unroll
    for (int o = 0; o < OUT_DIM; ++o)
        mx = fmaxf(mx, __shfl_sync(0xffffffffu, vo, o));
    float s = 0.f;
#pragma unroll
    for (int o = 0; o < OUT_DIM; ++o)
        s = __fadd_rn(s, expf(__fsub_rn(__shfl_sync(0xffffffffu, vo, o), mx)));
    if (lane < OUT_DIM)
        out[batch * OUT_DIM + lane] = __fsub_rn(__fsub_rn(vo, mx), logf(s));
}

// ---------------------------------------------------------------------------
extern "C" void kernel_launch(void* const* d_in, const int* in_sizes, int n_in,
                              void* d_out, int out_size) {
    const float* x     = (const float*)d_in[0];
    const float* w_in  = (const float*)d_in[1];
    const float* w_rec = (const float*)d_in[2];
    const float* w_out = (const float*)d_in[3];
    float* out = (float*)d_out;

    float* xw = nullptr;
    cudaGetSymbolAddress((void**)&xw, g_xw);

    // GEMM smem: 64*81 + 80*130 floats = 62.3 KB -> 3 CTA/SM
    size_t gemm_smem = (size_t)(64 * 81 + IN_DIM * WPAD) * sizeof(float);
    cudaFuncSetAttribute(xw_gemm_kernel, cudaFuncAttributeMaxDynamicSharedMemorySize,
                         (int)gemm_smem);
    xw_gemm_kernel<<<16000, 128, gemm_smem>>>(x, w_in, xw);

    size_t rec_smem = (size_t)(HID * HID + HID * 16) * sizeof(float);
    cudaFuncSetAttribute(snn_rec_kernel, cudaFuncAttributeMaxDynamicSharedMemorySize,
                         (int)rec_smem);
    snn_rec_kernel<<<128, 256, rec_smem>>>(xw, w_rec, w_out, out);
}

// round 14
// speedup vs baseline: 1.3958x; 1.0021x over previous
#include <cuda_runtime.h>
#include <math.h>

#define T_STEPS 1000
#define BATCH   1024
#define IN_DIM  80
#define HID     128
#define OUT_DIM 10
#define WPAD    130            // padded w row stride (even -> LDS.64 aligned)

#define REC_CTAS  148          // one CTA per SM
#define REC_WARPS 7            // 148*7 = 1036 >= 1024 batches

typedef unsigned long long ull;

__device__ float g_xw[(size_t)T_STEPS * BATCH * HID];   // 512 MB scratch

__device__ __forceinline__ ull pk2(float lo, float hi) {
    ull r; asm("mov.b64 %0, {%1, %2};" : "=l"(r) : "f"(lo), "f"(hi)); return r;
}
__device__ __forceinline__ ull ffma2(ull a, ull b, ull c) {
    ull d; asm("fma.rn.f32x2 %0, %1, %2, %3;" : "=l"(d) : "l"(a), "l"(b), "l"(c)); return d;
}
__device__ __forceinline__ ull fadd2(ull a, ull b) {
    ull d; asm("add.rn.f32x2 %0, %1, %2;" : "=l"(d) : "l"(a), "l"(b)); return d;
}

// ---------------------------------------------------------------------------
// Kernel A (R12 verbatim): xw[row][h] = ascending-k single-acc fma.rn.f32x2
// chain. CTA: 128 threads, 64 rows x 128 h; smem 62.3 KB -> 3 CTA/SM.
// ---------------------------------------------------------------------------
__global__ void __launch_bounds__(128) xw_gemm_kernel(const float* __restrict__ x,
                                                      const float* __restrict__ w_in,
                                                      float* __restrict__ xw) {
    extern __shared__ float sm[];
    float* xs = sm;                   // [64][81] padded rows
    float* ws = sm + 64 * 81;         // [80][WPAD] transposed: ws[k*WPAD+h]

    long row0 = (long)blockIdx.x * 64;
    int tid = threadIdx.x;

    const float* xsrc = x + row0 * IN_DIM;
    for (int idx = tid; idx < 64 * IN_DIM; idx += 128) {
        int r = idx / IN_DIM, k = idx - r * IN_DIM;
        xs[r * 81 + k] = xsrc[idx];
    }
    for (int idx = tid; idx < HID * IN_DIM; idx += 128) {
        int h = idx / IN_DIM, k = idx - h * IN_DIM;
        ws[k * WPAD + h] = w_in[idx];
    }
    __syncthreads();

    int hg = tid & 15;        // h-pairs 2hg + 32j (j<4)
    int rg = tid >> 4;        // rows rg + 8i (i<8)

    ull acc[8][4];
#pragma unroll
    for (int i = 0; i < 8; ++i)
#pragma unroll
        for (int j = 0; j < 4; ++j) acc[i][j] = 0ull;

#pragma unroll 10
    for (int k = 0; k < IN_DIM; ++k) {
        ull wp[4];
#pragma unroll
        for (int j = 0; j < 4; ++j)
            wp[j] = *(const ull*)&ws[k * WPAD + 2 * hg + 32 * j];
        float xv[8];
#pragma unroll
        for (int i = 0; i < 8; ++i)
            xv[i] = xs[(rg + 8 * i) * 81 + k];
#pragma unroll
        for (int i = 0; i < 8; ++i) {
            ull xd = pk2(xv[i], xv[i]);
#pragma unroll
            for (int j = 0; j < 4; ++j)
                acc[i][j] = ffma2(xd, wp[j], acc[i][j]);
        }
    }

#pragma unroll
    for (int i = 0; i < 8; ++i) {
        float* dst = &xw[(row0 + rg + 8 * i) * HID];
#pragma unroll
        for (int j = 0; j < 4; ++j)
            *(ull*)&dst[2 * hg + 32 * j] = acc[i][j];
    }
}

// ---------------------------------------------------------------------------
// Kernel B: recurrence. 148 CTAs x 224 threads (7 warps = 7 batches each,
// uniform 7 warps/SM on ALL SMs). Warp-per-batch, no barriers.
// Spike loop uses add.rn.f32x2 on (r0,r1),(r2,r3) pairs — per-component
// chains bitwise identical to scalar __fadd_rn chains.
// ---------------------------------------------------------------------------
__global__ void __launch_bounds__(224) snn_rec_kernel(const float* __restrict__ xw,
                                                      const float* __restrict__ w_rec,
                                                      const float* __restrict__ w_out,
                                                      float* __restrict__ out) {
    extern __shared__ float smem[];
    float* wr_p = smem;              // [128][128] permuted: wr_p[j*128+4*(h&31)+(h>>5)]
    float* wo_s = smem + HID * HID;  // [128][16]: wo_s[j*16+o] = w_out[o][j]

    int tid = threadIdx.x;
    for (int idx = tid; idx < HID * HID; idx += 224) {
        int h = idx >> 7, j = idx & 127;
        wr_p[(j << 7) + ((h & 31) << 2) + (h >> 5)] = w_rec[idx];
    }
    for (int idx = tid; idx < HID * 16; idx += 224) {
        int j = idx >> 4, o = idx & 15;
        wo_s[idx] = (o < OUT_DIM) ? w_out[o * HID + j] : 0.0f;
    }
    __syncthreads();

    int warp = tid >> 5, lane = tid & 31;
    int batch = blockIdx.x * REC_WARPS + warp;
    if (batch >= BATCH) return;

    float v0 = 0.f, v1 = 0.f, v2 = 0.f, v3 = 0.f;
    float c0 = 0.f, c1 = 0.f, c2 = 0.f, c3 = 0.f;
    float vo = 0.f, io = 0.f;

    const float* xwp = xw + (size_t)batch * HID + lane;

    // prefetch pipeline, distance 2
    float x0 = xwp[0], x1 = xwp[32], x2 = xwp[64], x3 = xwp[96];
    const float* p1 = xwp + (size_t)(BATCH * HID);
    float a0 = p1[0], a1 = p1[32], a2 = p1[64], a3 = p1[96];

    for (int t = 0; t < T_STEPS; ++t) {
        // --- LIF (exact reference expression order, separate rounding) ---
        float vd0 = __fadd_rn(v0, __fmul_rn(0.1f, __fadd_rn(__fsub_rn(0.f, v0), c0)));
        float vd1 = __fadd_rn(v1, __fmul_rn(0.1f, __fadd_rn(__fsub_rn(0.f, v1), c1)));
        float vd2 = __fadd_rn(v2, __fmul_rn(0.1f, __fadd_rn(__fsub_rn(0.f, v2), c2)));
        float vd3 = __fadd_rn(v3, __fmul_rn(0.1f, __fadd_rn(__fsub_rn(0.f, v3), c3)));
        float id0 = __fsub_rn(c0, __fmul_rn(0.2f, c0));
        float id1 = __fsub_rn(c1, __fmul_rn(0.2f, c1));
        float id2 = __fsub_rn(c2, __fmul_rn(0.2f, c2));
        float id3 = __fsub_rn(c3, __fmul_rn(0.2f, c3));
        bool z0 = __fsub_rn(vd0, 1.0f) > 0.0f;
        bool z1 = __fsub_rn(vd1, 1.0f) > 0.0f;
        bool z2 = __fsub_rn(vd2, 1.0f) > 0.0f;
        bool z3 = __fsub_rn(vd3, 1.0f) > 0.0f;
        v0 = z0 ? 0.f : vd0;
        v1 = z1 ? 0.f : vd1;
        v2 = z2 ? 0.f : vd2;
        v3 = z3 ? 0.f : vd3;

        unsigned m0 = __ballot_sync(0xffffffffu, z0);
        unsigned m1 = __ballot_sync(0xffffffffu, z1);
        unsigned m2 = __ballot_sync(0xffffffffu, z2);
        unsigned m3 = __ballot_sync(0xffffffffu, z3);

        // prefetch xw[t+2] (clamped)
        int t2 = (t + 2 < T_STEPS) ? t + 2 : T_STEPS - 1;
        const float* p2 = xwp + (size_t)t2 * (BATCH * HID);
        float b0 = p2[0], b1 = p2[32], b2 = p2[64], b3 = p2[96];

        // --- sparse z @ w_rec.T, ascending j; packed pair accumulators ---
        // r01 components = (r0, r1) scalar chains, r23 = (r2, r3): bitwise
        // identical to scalar __fadd_rn ascending-j chains per component.
        ull r01 = 0ull, r23 = 0ull;
        float os = 0.f;
#define SPIKES(MM, BASE)                                                        \
        while (MM) {                                                            \
            int b = __ffs(MM) - 1; MM &= MM - 1;                                \
            int j = (BASE) + b;                                                 \
            ulonglong2 w2 = *(const ulonglong2*)&wr_p[(j << 7) + (lane << 2)];  \
            r01 = fadd2(r01, w2.x);                                             \
            r23 = fadd2(r23, w2.y);                                             \
            if (lane < OUT_DIM) os = __fadd_rn(os, wo_s[(j << 4) + lane]);      \
        }
        SPIKES(m0, 0)
        SPIKES(m1, 32)
        SPIKES(m2, 64)
        SPIKES(m3, 96)
#undef SPIKES
        float r0, r1, r2, r3;
        asm("mov.b64 {%0, %1}, %2;" : "=f"(r0), "=f"(r1) : "l"(r01));
        asm("mov.b64 {%0, %1}, %2;" : "=f"(r2), "=f"(r3) : "l"(r23));

        c0 = __fadd_rn(__fadd_rn(id0, x0), r0);
        c1 = __fadd_rn(__fadd_rn(id1, x1), r1);
        c2 = __fadd_rn(__fadd_rn(id2, x2), r2);
        c3 = __fadd_rn(__fadd_rn(id3, x3), r3);

        // --- LI readout (lanes 0..9, o = lane) ---
        if (lane < OUT_DIM) {
            float ij = __fadd_rn(io, os);
            vo = __fadd_rn(vo, __fmul_rn(0.1f, __fadd_rn(__fsub_rn(0.f, vo), ij)));
            io = __fsub_rn(ij, __fmul_rn(0.2f, ij));
        }

        x0 = a0; x1 = a1; x2 = a2; x3 = a3;
        a0 = b0; a1 = b1; a2 = b2; a3 = b3;
    }

    // --- log_softmax over 10 outputs (ascending-o chains) ---
    float mx = -INFINITY;
#pragma unroll
    for (int o = 0; o < OUT_DIM; ++o)
        mx = fmaxf(mx, __shfl_sync(0xffffffffu, vo, o));
    float s = 0.f;
#pragma unroll
    for (int o = 0; o < OUT_DIM; ++o)
        s = __fadd_rn(s, expf(__fsub_rn(__shfl_sync(0xffffffffu, vo, o), mx)));
    if (lane < OUT_DIM)
        out[batch * OUT_DIM + lane] = __fsub_rn(__fsub_rn(vo, mx), logf(s));
}

// ---------------------------------------------------------------------------
extern "C" void kernel_launch(void* const* d_in, const int* in_sizes, int n_in,
                              void* d_out, int out_size) {
    const float* x     = (const float*)d_in[0];
    const float* w_in  = (const float*)d_in[1];
    const float* w_rec = (const float*)d_in[2];
    const float* w_out = (const float*)d_in[3];
    float* out = (float*)d_out;

    float* xw = nullptr;
    cudaGetSymbolAddress((void**)&xw, g_xw);

    // GEMM smem: 64*81 + 80*130 floats = 62.3 KB -> 3 CTA/SM
    size_t gemm_smem = (size_t)(64 * 81 + IN_DIM * WPAD) * sizeof(float);
    cudaFuncSetAttribute(xw_gemm_kernel, cudaFuncAttributeMaxDynamicSharedMemorySize,
                         (int)gemm_smem);
    xw_gemm_kernel<<<16000, 128, gemm_smem>>>(x, w_in, xw);

    size_t rec_smem = (size_t)(HID * HID + HID * 16) * sizeof(float);
    cudaFuncSetAttribute(snn_rec_kernel, cudaFuncAttributeMaxDynamicSharedMemorySize,
                         (int)rec_smem);
    snn_rec_kernel<<<REC_CTAS, REC_WARPS * 32, rec_smem>>>(xw, w_rec, w_out, out);
}